// round 13
// baseline (speedup 1.0000x reference)
#include <cuda_runtime.h>
#include <cstdint>

#define K1REAL  100
#define HDIM    256
#define TILE_M  32
#define THREADS 256            // 8 warps; warp w = m32 x n[w*32, w*32+32)
#define NCHUNK  20             // k32 chunks: L1 4 (k pad 128), L2 8, L3 8

// A act buffers: frag-linear int8 digits, [chunk g][digit d][m16 t][lane]16B
// per-chunk 2048B; per layer <= 8 chunks = 16KB; double buffered
#define SMEM_TOTAL 32768

// B frag-linear int8 digits: [g][slice s][d][pair p][lane]16B = 16KB/chunk
__device__ int8_t WCH8[(size_t)21 * 16384];   // slot 20 = prefetch pad

__device__ __forceinline__ uint32_t smem_u32(const void* p) {
    uint32_t a;
    asm("{ .reg .u64 t; cvta.to.shared.u64 t, %1; cvt.u32.u64 %0, t; }" : "=r"(a) : "l"(p));
    return a;
}
__device__ __forceinline__ void lds128(uint32_t r[4], uint32_t addr) {
    asm volatile("ld.shared.v4.u32 {%0,%1,%2,%3}, [%4];"
                 : "=r"(r[0]), "=r"(r[1]), "=r"(r[2]), "=r"(r[3]) : "r"(addr));
}
__device__ __forceinline__ void imma(int d[4], const uint32_t a[4],
                                     uint32_t b0, uint32_t b1) {
    asm volatile(
        "mma.sync.aligned.m16n8k32.row.col.s32.s8.s8.s32 "
        "{%0,%1,%2,%3}, {%4,%5,%6,%7}, {%8,%9}, {%0,%1,%2,%3};"
        : "+r"(d[0]), "+r"(d[1]), "+r"(d[2]), "+r"(d[3])
        : "r"(a[0]), "r"(a[1]), "r"(a[2]), "r"(a[3]), "r"(b0), "r"(b1));
}
__device__ __forceinline__ float tanh_fast(float x) {
    float y; asm("tanh.approx.f32 %0, %1;" : "=f"(y) : "f"(x)); return y;
}
// two-digit int8 quantization of u in [-1,1]: u ~= (a1 + a2/128)/127
__device__ __forceinline__ void quant2(float u, int& a1, int& a2) {
    float s = u * 127.0f;
    a1 = __float2int_rn(s);
    a2 = __float2int_rn((s - (float)a1) * 128.0f);
}

// ---- weight pre-split: W[k][n] -> B-fragment-linear two-digit int8 ----
__global__ void wsplit_kernel(const float* __restrict__ W1,
                              const float* __restrict__ W2,
                              const float* __restrict__ W3) {
    int n = threadIdx.x;
    int kidx = blockIdx.x;                  // 0..639 padded k
    const float* W; int kk, Kreal, g; float wmax;
    if (kidx < 128)      { kk = kidx;       W = W1; Kreal = K1REAL; g = kk >> 5;       wmax = 0.1f; }
    else if (kidx < 384) { kk = kidx - 128; W = W2; Kreal = HDIM;   g = 4  + (kk >> 5); wmax = 0.0625f; }
    else                 { kk = kidx - 384; W = W3; Kreal = HDIM;   g = 12 + (kk >> 5); wmax = 0.0625f; }
    float v = ((kk < Kreal) ? W[kk * HDIM + n] : 0.0f) / wmax;
    int b1i, b2i; quant2(v, b1i, b2i);
    int kap = kk & 31;
    int s = n >> 5, t = (n & 31) >> 3, h = kap >> 4;
    int L = (n & 7) * 4 + ((kap & 15) >> 2);
    int p = t >> 1, rr = (t & 1) * 2 + h;
    size_t off = (size_t)g * 16384 + (size_t)s * 2048 + (size_t)p * 512
               + (size_t)L * 16 + (size_t)rr * 4 + (size_t)(kap & 3);
    WCH8[off]        = (int8_t)b1i;
    WCH8[off + 1024] = (int8_t)b2i;     // digit-2 image (d stride 1024)
}

// ---- main kernel ----
__global__ void __launch_bounds__(THREADS, 2)
gnn_imma_kernel(const float* __restrict__ ea,
                const float* __restrict__ b1, const float* __restrict__ b2,
                const float* __restrict__ b3,
                const float* __restrict__ W4, const float* __restrict__ b4,
                float* __restrict__ out, int ntot)
{
    extern __shared__ char smem[];
    const uint32_t sbase = smem_u32(smem);
    const int tid = threadIdx.x, lane = tid & 31, wid = tid >> 5;
    const int row0 = blockIdx.x * TILE_M;
    const int r = lane >> 2, cp2 = (lane & 3) * 2;

    // prologue: e-tile -> buf0 frag-linear digits (chunks 0..3, k pad 128)
#pragma unroll
    for (int i = 0; i < 16; i++) {
        int idx = tid + i * THREADS;        // 32*128
        int m = idx >> 7, k = idx & 127;
        int row = row0 + m;
        float v = (k < K1REAL && row < ntot) ? ea[(size_t)row * K1REAL + k] : 0.0f;
        int a1, a2; quant2(v, a1, a2);      // e in [0,1): scale X=1
        int t = m >> 4, rho = m & 15, g = k >> 5, kap = k & 31;
        int L = (rho & 7) * 4 + ((kap & 15) >> 2);
        int j = (kap >> 4) * 2 + (rho >> 3);
        int off = g * 2048 + t * 512 + L * 16 + j * 4 + (kap & 3);
        smem[off]        = (char)a1;
        smem[off + 1024] = (char)a2;
    }
    __syncthreads();

    const int8_t* wlane = WCH8 + (size_t)wid * 2048 + (size_t)lane * 16;

    int acc1[2][4][4], acc2[2][4][4];
#pragma unroll
    for (int mt = 0; mt < 2; mt++)
#pragma unroll
        for (int nt = 0; nt < 4; nt++)
#pragma unroll
            for (int q = 0; q < 4; q++) { acc1[mt][nt][q] = 0; acc2[mt][nt][q] = 0; }

    // preload chunk-0 B digit-1 fragments
    uint4 pb0 = __ldg((const uint4*)wlane);
    uint4 pb1 = __ldg((const uint4*)(wlane + 512));

    int gbase = 0;
    uint32_t rd = 0, wr = 16384;
    const float C1 = 0.1f / 16129.0f, C2 = 0.0625f / 16129.0f;

#pragma unroll
    for (int l = 0; l < 3; l++) {
        const int nch = (l == 0) ? 4 : 8;
        for (int ci = 0; ci < nch; ci++) {
            const int8_t* wp = wlane + (size_t)(gbase + ci) * 16384;
            uint4 c0 = __ldg((const uint4*)(wp + 1024));          // digit-2, tiles 0,1
            uint4 c1 = __ldg((const uint4*)(wp + 1024 + 512));    // digit-2, tiles 2,3
            uint4 n0 = __ldg((const uint4*)(wp + 16384));         // next digit-1
            uint4 n1 = __ldg((const uint4*)(wp + 16384 + 512));
            uint32_t bb1[8] = { pb0.x, pb0.y, pb0.z, pb0.w, pb1.x, pb1.y, pb1.z, pb1.w };
            uint32_t bb2[8] = { c0.x, c0.y, c0.z, c0.w, c1.x, c1.y, c1.z, c1.w };

            uint32_t a1f[2][4], a2f[2][4];
            uint32_t ab = sbase + rd + (uint32_t)ci * 2048u + (uint32_t)lane * 16u;
            lds128(a1f[0], ab);               // digit1 tile0
            lds128(a1f[1], ab + 512);         // digit1 tile1
            lds128(a2f[0], ab + 1024);        // digit2 tile0
            lds128(a2f[1], ab + 1536);        // digit2 tile1

#pragma unroll
            for (int nt = 0; nt < 4; nt++) {
                imma(acc1[0][nt], a1f[0], bb1[nt * 2], bb1[nt * 2 + 1]);
                imma(acc1[1][nt], a1f[1], bb1[nt * 2], bb1[nt * 2 + 1]);
            }
#pragma unroll
            for (int nt = 0; nt < 4; nt++) {
                imma(acc2[0][nt], a1f[0], bb2[nt * 2], bb2[nt * 2 + 1]);
                imma(acc2[1][nt], a1f[1], bb2[nt * 2], bb2[nt * 2 + 1]);
            }
#pragma unroll
            for (int nt = 0; nt < 4; nt++) {
                imma(acc2[0][nt], a2f[0], bb1[nt * 2], bb1[nt * 2 + 1]);
                imma(acc2[1][nt], a2f[1], bb1[nt * 2], bb1[nt * 2 + 1]);
            }
            pb0 = n0; pb1 = n1;
        }
        gbase += nch;

        if (l < 2) {
            const float C = (l == 0) ? C1 : C2;
            const float* bl = (l == 0) ? b1 : b2;
#pragma unroll
            for (int nt = 0; nt < 4; nt++) {
                int n = wid * 32 + nt * 8 + cp2;
                float bn0 = __ldg(bl + n), bn1 = __ldg(bl + n + 1);
                int kap = nt * 8 + cp2;
#pragma unroll
                for (int mt = 0; mt < 2; mt++)
#pragma unroll
                    for (int dp = 0; dp < 2; dp++) {
                        float f0 = (float)acc1[mt][nt][dp * 2]
                                 + (float)acc2[mt][nt][dp * 2] * 0.0078125f;
                        float f1 = (float)acc1[mt][nt][dp * 2 + 1]
                                 + (float)acc2[mt][nt][dp * 2 + 1] * 0.0078125f;
                        float t0 = tanh_fast(f0 * C + bn0);
                        float t1 = tanh_fast(f1 * C + bn1);
                        t0 = fminf(fmaxf(t0, -1.0f), 1.0f);
                        t1 = fminf(fmaxf(t1, -1.0f), 1.0f);
                        int q0a, q0b, q1a, q1b;
                        quant2(t0, q0a, q0b); quant2(t1, q1a, q1b);
                        int L = r * 4 + ((kap & 15) >> 2);
                        int j = (kap >> 4) * 2 + dp;
                        uint32_t off = wr + (uint32_t)(wid * 2048 + mt * 512
                                     + L * 16 + j * 4 + (kap & 3));
                        unsigned short d1 = (unsigned short)((q0a & 0xFF) | ((q1a & 0xFF) << 8));
                        unsigned short d2 = (unsigned short)((q0b & 0xFF) | ((q1b & 0xFF) << 8));
                        asm volatile("st.shared.u16 [%0], %1;" :: "r"(sbase + off), "h"(d1));
                        asm volatile("st.shared.u16 [%0], %1;" :: "r"(sbase + off + 1024u), "h"(d2));
                        acc1[mt][nt][dp * 2] = 0; acc1[mt][nt][dp * 2 + 1] = 0;
                        acc2[mt][nt][dp * 2] = 0; acc2[mt][nt][dp * 2 + 1] = 0;
                    }
            }
            __syncthreads();                  // epilogue writes visible
            uint32_t tmp = rd; rd = wr; wr = tmp;
        } else {
            // fused layer-3 epilogue + layer 4
            float part[4] = {0.f, 0.f, 0.f, 0.f};   // idx = mt*2+dp
#pragma unroll
            for (int nt = 0; nt < 4; nt++) {
                int n = wid * 32 + nt * 8 + cp2;
                float bn0 = __ldg(b3 + n), bn1 = __ldg(b3 + n + 1);
                float2 w2 = __ldg((const float2*)(W4 + n));
#pragma unroll
                for (int mt = 0; mt < 2; mt++)
#pragma unroll
                    for (int dp = 0; dp < 2; dp++) {
                        float f0 = (float)acc1[mt][nt][dp * 2]
                                 + (float)acc2[mt][nt][dp * 2] * 0.0078125f;
                        float f1 = (float)acc1[mt][nt][dp * 2 + 1]
                                 + (float)acc2[mt][nt][dp * 2 + 1] * 0.0078125f;
                        float t0 = tanh_fast(f0 * C2 + bn0);
                        float t1 = tanh_fast(f1 * C2 + bn1);
                        part[mt * 2 + dp] += t0 * w2.x + t1 * w2.y;
                    }
            }
#pragma unroll
            for (int i = 0; i < 4; i++) {
                part[i] += __shfl_xor_sync(0xffffffff, part[i], 1);
                part[i] += __shfl_xor_sync(0xffffffff, part[i], 2);
            }
            float* psm = (float*)(smem + wr);   // wr buffer free (l1 reads done)
            if ((lane & 3) == 0) {
#pragma unroll
                for (int mt = 0; mt < 2; mt++)
#pragma unroll
                    for (int dp = 0; dp < 2; dp++)
                        psm[wid * 32 + mt * 16 + r + dp * 8] = part[mt * 2 + dp];
            }
            __syncthreads();
            if (tid < TILE_M) {
                float s = 0.0f;
#pragma unroll
                for (int w = 0; w < 8; w++) s += psm[w * 32 + tid];
                float z = s + __ldg(b4);
                int row = row0 + tid;
                if (row < ntot) out[row] = 1.0f / (1.0f + expf(-z));
            }
        }
    }
}

extern "C" void kernel_launch(void* const* d_in, const int* in_sizes, int n_in,
                              void* d_out, int out_size)
{
    // Inputs: x, edge_index, edge_attr, W1, b1, W2, b2, W3, b3, W4, b4
    const float* ea = (const float*)d_in[2];
    const float* W1 = (const float*)d_in[3];
    const float* b1 = (const float*)d_in[4];
    const float* W2 = (const float*)d_in[5];
    const float* b2 = (const float*)d_in[6];
    const float* W3 = (const float*)d_in[7];
    const float* b3 = (const float*)d_in[8];
    const float* W4 = (const float*)d_in[9];
    const float* b4 = (const float*)d_in[10];
    float* out = (float*)d_out;

    int ntot = out_size;                              // 500000
    int grid = (ntot + TILE_M - 1) / TILE_M;          // 15625

    wsplit_kernel<<<640, 256>>>(W1, W2, W3);

    cudaFuncSetAttribute(gnn_imma_kernel,
                         cudaFuncAttributeMaxDynamicSharedMemorySize, SMEM_TOTAL);
    gnn_imma_kernel<<<grid, THREADS, SMEM_TOTAL>>>(ea, b1, b2, b3, W4, b4, out, ntot);
}

// round 14
// speedup vs baseline: 8.4149x; 8.4149x over previous
#include <cuda_runtime.h>
#include <cuda_fp16.h>
#include <cstdint>

#define K1REAL  100
#define HDIM    256
#define TILE_M  64
#define THREADS 256            // 8 warps; warp w owns m0..63 x n[w*32, w*32+32)
#define NCHUNK  39             // k16 chunks: L1 7 (k pad 112), L2 16, L3 16

#define SMEM_TOTAL 32768       // single fp16 act image, 64 x 512B XOR-swizzled

// fragment-linear fp16 weights (40 slots; slot 39 = prefetch-overread pad)
// per chunk 8192B: [slice s(8)][1024B]: q(2)*512 + L*16 + j*4 + (k&1)*2
__device__ __half WCH[(size_t)40 * 4096];

__device__ __forceinline__ uint32_t smem_u32(const void* p) {
    uint32_t a;
    asm("{ .reg .u64 t; cvta.to.shared.u64 t, %1; cvt.u32.u64 %0, t; }" : "=r"(a) : "l"(p));
    return a;
}
__device__ __forceinline__ void ldsm_x4(uint32_t r[4], uint32_t addr) {
    asm volatile("ldmatrix.sync.aligned.m8n8.x4.shared.b16 {%0,%1,%2,%3}, [%4];"
                 : "=r"(r[0]), "=r"(r[1]), "=r"(r[2]), "=r"(r[3]) : "r"(addr));
}
__device__ __forceinline__ void mma_f16(float d[4], const uint32_t a[4],
                                        uint32_t b0, uint32_t b1) {
    asm volatile(
        "mma.sync.aligned.m16n8k16.row.col.f32.f16.f16.f32 "
        "{%0,%1,%2,%3}, {%4,%5,%6,%7}, {%8,%9}, {%0,%1,%2,%3};"
        : "+f"(d[0]), "+f"(d[1]), "+f"(d[2]), "+f"(d[3])
        : "r"(a[0]), "r"(a[1]), "r"(a[2]), "r"(a[3]), "r"(b0), "r"(b1));
}
__device__ __forceinline__ float tanh_fast(float x) {
    float y; asm("tanh.approx.f32 %0, %1;" : "=f"(y) : "f"(x)); return y;
}
__device__ __forceinline__ uint32_t pack_h2(float a, float b) {
    __half2 t = __halves2half2(__float2half(a), __float2half(b));
    return *reinterpret_cast<uint32_t*>(&t);
}
// act element (m, k): byte offset m*512 + ((k*2) ^ ((m&7)<<4))  (verified R8-R12)
__device__ __forceinline__ uint32_t act_off(int m, int k) {
    return (uint32_t)m * 512u + (((uint32_t)k * 2u) ^ (((uint32_t)m & 7u) << 4));
}

// ---- weight prep: W[k][n] -> fragment-linear fp16 (mapping verified R11/R12) ----
__global__ void wsplit_kernel(const float* __restrict__ W1,
                              const float* __restrict__ W2,
                              const float* __restrict__ W3) {
    int n = threadIdx.x;
    int kidx = blockIdx.x;                  // 0..623 padded k (L1 pad 112)
    const float* W; int kk, Kreal, g;
    if (kidx < 112)      { kk = kidx;       W = W1; Kreal = K1REAL; g = kk >> 4; }
    else if (kidx < 368) { kk = kidx - 112; W = W2; Kreal = HDIM;   g = 7  + (kk >> 4); }
    else                 { kk = kidx - 368; W = W3; Kreal = HDIM;   g = 23 + (kk >> 4); }
    float w = (kk < Kreal) ? W[kk * HDIM + n] : 0.0f;
    int kc = kk & 15;
    int s  = n >> 5, nn = n & 31, q = nn >> 4;
    int j  = ((nn >> 3) & 1) * 2 + ((kc >> 3) & 1);
    int L  = (nn & 7) * 4 + ((kc & 7) >> 1);
    size_t base = (size_t)g * 8192 + (size_t)s * 1024
                + (size_t)q * 512 + (size_t)L * 16 + (size_t)j * 4 + (size_t)(kc & 1) * 2;
    *(__half*)((char*)WCH + base) = __float2half(w);
}

// ---- main kernel ----
__global__ void __launch_bounds__(THREADS, 2)
gnn_mma_kernel(const float* __restrict__ ea,
               const float* __restrict__ b1, const float* __restrict__ b2,
               const float* __restrict__ b3,
               const float* __restrict__ W4, const float* __restrict__ b4,
               float* __restrict__ out, int ntot)
{
    extern __shared__ char smem[];
    const uint32_t sbase = smem_u32(smem);
    const int tid = threadIdx.x, lane = tid & 31, wid = tid >> 5;
    const int row0 = blockIdx.x * TILE_M;

    // e-tile: [m][k0..127] fp16, swizzled (k>=100 zero; only k<112 used)
#pragma unroll
    for (int i = 0; i < 32; i++) {
        int idx = tid + i * THREADS;        // 64*128
        int m = idx >> 7, k = idx & 127;
        int row = row0 + m;
        float v = (k < K1REAL && row < ntot) ? ea[(size_t)row * K1REAL + k] : 0.0f;
        *(__half*)(smem + act_off(m, k)) = __float2half(v);
    }
    __syncthreads();

    // A ldsm addressing (loop-invariant)
    const int midx = lane >> 3, l7 = lane & 7;
    const int arow = (midx & 1) * 8 + l7;               // 0..15
    const uint32_t a_base = (uint32_t)arow * 512u;
    const uint32_t a_sw   = ((uint32_t)arow & 7u) << 4;
    const uint32_t a_k2   = (uint32_t)(midx >> 1) * 16u;

    const char* wlane = (const char*)WCH + (size_t)wid * 1024 + (size_t)lane * 16;

    float acc[4][4][4];
#pragma unroll
    for (int mt = 0; mt < 4; mt++)
#pragma unroll
        for (int nt = 0; nt < 4; nt++)
#pragma unroll
            for (int x = 0; x < 4; x++) acc[mt][nt][x] = 0.0f;

    const int r = lane >> 2, cp2 = (lane & 3) * 2;
    int gbase = 0;

    // preload chunk-0 B fragments
    uint32_t bh[8];
    {
        uint4 t0 = __ldg((const uint4*)wlane);
        uint4 t1 = __ldg((const uint4*)(wlane + 512));
        bh[0]=t0.x; bh[1]=t0.y; bh[2]=t0.z; bh[3]=t0.w;
        bh[4]=t1.x; bh[5]=t1.y; bh[6]=t1.z; bh[7]=t1.w;
    }

#pragma unroll
    for (int l = 0; l < 3; l++) {
        const int nch = (l == 0) ? 7 : 16;
        for (int ci = 0; ci < nch; ci++) {
            const int g = gbase + ci;
            // prefetch next chunk's B fragments (slot 39 = pad)
            const char* wpn = wlane + (size_t)(g + 1) * 8192;
            uint4 p0 = __ldg((const uint4*)wpn);
            uint4 p1 = __ldg((const uint4*)(wpn + 512));

            const uint32_t abase = sbase + a_base + (((uint32_t)ci * 32u + a_k2) ^ a_sw);
            uint32_t a[16];
#pragma unroll
            for (int mt = 0; mt < 4; mt++) ldsm_x4(a + mt * 4, abase + mt * 8192);
#pragma unroll
            for (int nt = 0; nt < 4; nt++) {
                uint32_t bx = bh[(nt >> 1) * 4 + (nt & 1) * 2];
                uint32_t by = bh[(nt >> 1) * 4 + (nt & 1) * 2 + 1];
#pragma unroll
                for (int mt = 0; mt < 4; mt++) mma_f16(acc[mt][nt], a + mt * 4, bx, by);
            }
            bh[0]=p0.x; bh[1]=p0.y; bh[2]=p0.z; bh[3]=p0.w;
            bh[4]=p1.x; bh[5]=p1.y; bh[6]=p1.z; bh[7]=p1.w;
        }
        gbase += nch;

        __syncthreads();   // all act reads of this layer done

        if (l < 2) {
            const float* bl = (l == 0) ? b1 : b2;
#pragma unroll
            for (int nt = 0; nt < 4; nt++) {
                int n = wid * 32 + nt * 8 + cp2;
                float bn0 = __ldg(bl + n), bn1 = __ldg(bl + n + 1);
#pragma unroll
                for (int mt = 0; mt < 4; mt++)
#pragma unroll
                    for (int dp = 0; dp < 2; dp++) {
                        int m = mt * 16 + r + dp * 8;
                        float t0 = tanh_fast(acc[mt][nt][dp * 2]     + bn0);
                        float t1 = tanh_fast(acc[mt][nt][dp * 2 + 1] + bn1);
                        *(uint32_t*)(smem + act_off(m, n)) = pack_h2(t0, t1);
                        acc[mt][nt][dp * 2] = 0.0f; acc[mt][nt][dp * 2 + 1] = 0.0f;
                    }
            }
            __syncthreads();   // act writes visible before next layer's ldsm
        } else {
            // fused layer-3 epilogue + layer 4 (exact fp32 path, verified R12)
            float part[8];     // idx = mt*2 + dp, m = mt*16 + r + dp*8
#pragma unroll
            for (int i = 0; i < 8; i++) part[i] = 0.0f;
#pragma unroll
            for (int nt = 0; nt < 4; nt++) {
                int n = wid * 32 + nt * 8 + cp2;
                float bn0 = __ldg(b3 + n), bn1 = __ldg(b3 + n + 1);
                float2 w2 = __ldg((const float2*)(W4 + n));
#pragma unroll
                for (int mt = 0; mt < 4; mt++)
#pragma unroll
                    for (int dp = 0; dp < 2; dp++) {
                        float t0 = tanh_fast(acc[mt][nt][dp * 2]     + bn0);
                        float t1 = tanh_fast(acc[mt][nt][dp * 2 + 1] + bn1);
                        part[mt * 2 + dp] += t0 * w2.x + t1 * w2.y;
                    }
            }
#pragma unroll
            for (int i = 0; i < 8; i++) {
                part[i] += __shfl_xor_sync(0xffffffff, part[i], 1);
                part[i] += __shfl_xor_sync(0xffffffff, part[i], 2);
            }
            float* psm = (float*)smem;   // act area free after barrier above
            if ((lane & 3) == 0) {
#pragma unroll
                for (int mt = 0; mt < 4; mt++)
#pragma unroll
                    for (int dp = 0; dp < 2; dp++)
                        psm[wid * 64 + mt * 16 + r + dp * 8] = part[mt * 2 + dp];
            }
            __syncthreads();
            if (tid < TILE_M) {
                float s = 0.0f;
#pragma unroll
                for (int w = 0; w < 8; w++) s += psm[w * 64 + tid];
                float z = s + __ldg(b4);
                int row = row0 + tid;
                if (row < ntot) out[row] = 1.0f / (1.0f + expf(-z));
            }
        }
    }
}

extern "C" void kernel_launch(void* const* d_in, const int* in_sizes, int n_in,
                              void* d_out, int out_size)
{
    // Inputs: x, edge_index, edge_attr, W1, b1, W2, b2, W3, b3, W4, b4
    const float* ea = (const float*)d_in[2];
    const float* W1 = (const float*)d_in[3];
    const float* b1 = (const float*)d_in[4];
    const float* W2 = (const float*)d_in[5];
    const float* b2 = (const float*)d_in[6];
    const float* W3 = (const float*)d_in[7];
    const float* b3 = (const float*)d_in[8];
    const float* W4 = (const float*)d_in[9];
    const float* b4 = (const float*)d_in[10];
    float* out = (float*)d_out;

    int ntot = out_size;                              // 500000
    int grid = (ntot + TILE_M - 1) / TILE_M;          // 7813

    wsplit_kernel<<<624, 256>>>(W1, W2, W3);

    cudaFuncSetAttribute(gnn_mma_kernel,
                         cudaFuncAttributeMaxDynamicSharedMemorySize, SMEM_TOTAL);
    gnn_mma_kernel<<<grid, THREADS, SMEM_TOTAL>>>(ea, b1, b2, b3, W4, b4, out, ntot);
}